// round 4
// baseline (speedup 1.0000x reference)
#include <cuda_runtime.h>

#define CDIV(a,b) (((a)+(b)-1)/(b))

// ---------------- problem constants (fixed by setup_inputs) ----------------
#define KDIM   256
#define NT1C   25000
#define NT2C   5000
#define N0C    100000
#define E1CAP  400000
#define E2CAP  100000
#define NEG_SLOPE 0.2f

// ---------------- static scratch (no allocations allowed) ----------------
__device__ float g_xs1[(size_t)N0C * 256];   // x @ W1_src         (102.4 MB)
__device__ float g_h  [(size_t)NT1C * 256];  // skip1 buf -> h     (25.6 MB)
__device__ float g_xs2[(size_t)NT1C * 64];   // h @ W2_src
__device__ float g_o  [(size_t)NT2C * 64];   // skip2 buf -> o
__device__ float g_as1[(size_t)N0C * 4];
__device__ float g_ad1[NT1C * 4];
__device__ float g_as2[NT1C];
__device__ float g_ad2[NT2C];
__device__ float g_vS1[4 * 256];
__device__ float g_vD1[4 * 256];
__device__ float g_vS2[256];
__device__ float g_vD2[256];
__device__ float g_comb1[256];
__device__ float g_comb2[64];
__device__ int g_cnt1[NT1C];
__device__ int g_off1[NT1C + 1];
__device__ int g_cur1[NT1C];
__device__ int g_eid1[E1CAP];
__device__ int g_cnt2[NT2C];
__device__ int g_off2[NT2C + 1];
__device__ int g_cur2[NT2C];
__device__ int g_eid2[E2CAP];

// ---------------- fold: attention projection vectors + combined biases ----
// a_s[i,h] = sum_k x[i,k] * (sum_d W_src[k, h*64+d] * att_src[h,d])  (exact)
__global__ void fold_kernel(const float* __restrict__ W1s, const float* __restrict__ W1d,
                            const float* __restrict__ a1s, const float* __restrict__ a1d,
                            const float* __restrict__ b1,  const float* __restrict__ s1b,
                            const float* __restrict__ W2s, const float* __restrict__ W2d,
                            const float* __restrict__ a2s, const float* __restrict__ a2d,
                            const float* __restrict__ b2,  const float* __restrict__ s2b)
{
    int k = threadIdx.x;  // 0..255
    #pragma unroll
    for (int h = 0; h < 4; h++) {
        float ss = 0.f, sd = 0.f;
        for (int d = 0; d < 64; d++) {
            ss += W1s[k * 256 + h * 64 + d] * a1s[h * 64 + d];
            sd += W1d[k * 256 + h * 64 + d] * a1d[h * 64 + d];
        }
        g_vS1[h * 256 + k] = ss;
        g_vD1[h * 256 + k] = sd;
    }
    float s2 = 0.f, d2 = 0.f;
    for (int d = 0; d < 64; d++) {
        s2 += W2s[k * 64 + d] * a2s[d];
        d2 += W2d[k * 64 + d] * a2d[d];
    }
    g_vS2[k] = s2;
    g_vD2[k] = d2;
    g_comb1[k] = b1[k] + s1b[k];
    if (k < 64) g_comb2[k] = b2[k] + s2b[k];
}

// ---------------- CSR build ----------------
__global__ void zero_counts()
{
    int i = blockIdx.x * blockDim.x + threadIdx.x;
    if (i < NT1C) g_cnt1[i] = 0;
    if (i < NT2C) g_cnt2[i] = 0;
}

__global__ void count_kernel(const int* __restrict__ dst, int* __restrict__ cnt, int E)
{
    int e = blockIdx.x * blockDim.x + threadIdx.x;
    if (e < E) atomicAdd(&cnt[dst[e]], 1);
}

// single-block scan: off[0..n] exclusive offsets, cur[i] = off[i] (fill cursors)
__global__ void scan_kernel(const int* __restrict__ cnt, int* __restrict__ off,
                            int* __restrict__ cur, int n)
{
    __shared__ int buf[1024];
    __shared__ int carry;
    int t = threadIdx.x;
    if (t == 0) { carry = 0; off[0] = 0; }
    __syncthreads();
    for (int base = 0; base < n; base += 1024) {
        int i = base + t;
        int v = (i < n) ? cnt[i] : 0;
        buf[t] = v;
        __syncthreads();
        #pragma unroll
        for (int d = 1; d < 1024; d <<= 1) {
            int x = (t >= d) ? buf[t - d] : 0;
            __syncthreads();
            buf[t] += x;
            __syncthreads();
        }
        if (i < n) {
            int incl = carry + buf[t];
            off[i + 1] = incl;
            cur[i] = incl - v;
        }
        __syncthreads();
        if (t == 0) carry += buf[1023];
        __syncthreads();
    }
}

__global__ void fill_kernel(const int* __restrict__ dst, int* __restrict__ cur,
                            int* __restrict__ eid, int E)
{
    int e = blockIdx.x * blockDim.x + threadIdx.x;
    if (e < E) {
        int p = atomicAdd(&cur[dst[e]], 1);
        eid[p] = e;
    }
}

// ---------------- SGEMM: C[M,N] = A[M,256] @ B[256,N] (+ bias) ----------------
// BM=128 BN=64 BK=32, 256 threads, 8x4 microtile
#define GBM 128
#define GBN 64
#define GBK 32
__global__ __launch_bounds__(256) void sgemm_k256(
    const float* __restrict__ A, const float* __restrict__ B,
    const float* __restrict__ bias, float* __restrict__ C, int M, int N)
{
    __shared__ float As[GBK][GBM + 4];
    __shared__ float Bs[GBK][GBN];
    int tid = threadIdx.x;
    int tx = tid & 15;   // N direction (16 * 4 = 64)
    int ty = tid >> 4;   // M direction (16 * 8 = 128)
    int bm0 = blockIdx.y * GBM;
    int bn0 = blockIdx.x * GBN;

    float acc[8][4];
    #pragma unroll
    for (int i = 0; i < 8; i++)
        #pragma unroll
        for (int j = 0; j < 4; j++) acc[i][j] = 0.f;

    for (int k0 = 0; k0 < KDIM; k0 += GBK) {
        // A tile: 128x32 = 1024 float4, 4 per thread; store transposed
        #pragma unroll
        for (int u = 0; u < 4; u++) {
            int j = tid + u * 256;       // 0..1023
            int r = j >> 3;              // row in tile (8 float4 per row)
            int c4 = j & 7;
            int row = bm0 + r;
            float4 v = make_float4(0.f, 0.f, 0.f, 0.f);
            if (row < M) v = *(const float4*)(A + (size_t)row * KDIM + k0 + c4 * 4);
            As[c4 * 4 + 0][r] = v.x;
            As[c4 * 4 + 1][r] = v.y;
            As[c4 * 4 + 2][r] = v.z;
            As[c4 * 4 + 3][r] = v.w;
        }
        // B tile: 32x64 = 512 float4, 2 per thread
        #pragma unroll
        for (int u = 0; u < 2; u++) {
            int j = tid + u * 256;       // 0..511
            int r = j >> 4;              // 16 float4 per row
            int c4 = j & 15;
            *(float4*)&Bs[r][c4 * 4] =
                *(const float4*)(B + (size_t)(k0 + r) * N + bn0 + c4 * 4);
        }
        __syncthreads();
        #pragma unroll
        for (int k = 0; k < GBK; k++) {
            float a[8], b[4];
            *(float4*)&a[0] = *(const float4*)&As[k][ty * 8];
            *(float4*)&a[4] = *(const float4*)&As[k][ty * 8 + 4];
            *(float4*)&b[0] = *(const float4*)&Bs[k][tx * 4];
            #pragma unroll
            for (int i = 0; i < 8; i++)
                #pragma unroll
                for (int j = 0; j < 4; j++)
                    acc[i][j] += a[i] * b[j];
        }
        __syncthreads();
    }

    float bv[4] = {0.f, 0.f, 0.f, 0.f};
    if (bias) *(float4*)bv = *(const float4*)(bias + bn0 + tx * 4);
    #pragma unroll
    for (int i = 0; i < 8; i++) {
        int row = bm0 + ty * 8 + i;
        if (row < M) {
            float4 v;
            v.x = acc[i][0] + bv[0];
            v.y = acc[i][1] + bv[1];
            v.z = acc[i][2] + bv[2];
            v.w = acc[i][3] + bv[3];
            *(float4*)(C + (size_t)row * N + bn0 + tx * 4) = v;
        }
    }
}

// ---------------- skinny row-dot: out[M,H] = X[M,256] @ V^T (V is [H,256]) ----
template <int H>
__global__ void rowdot_kernel(const float* __restrict__ X, const float* __restrict__ V,
                              float* __restrict__ out, int M)
{
    int warp = (blockIdx.x * blockDim.x + threadIdx.x) >> 5;
    int lane = threadIdx.x & 31;
    if (warp >= M) return;
    const float* xr = X + (size_t)warp * 256 + lane * 8;
    float4 x0 = *(const float4*)xr;
    float4 x1 = *(const float4*)(xr + 4);
    float r[H];
    #pragma unroll
    for (int h = 0; h < H; h++) {
        const float* vr = V + h * 256 + lane * 8;
        float4 v0 = *(const float4*)vr;
        float4 v1 = *(const float4*)(vr + 4);
        float s = x0.x * v0.x + x0.y * v0.y + x0.z * v0.z + x0.w * v0.w +
                  x1.x * v1.x + x1.y * v1.y + x1.z * v1.z + x1.w * v1.w;
        #pragma unroll
        for (int o = 16; o; o >>= 1) s += __shfl_xor_sync(0xffffffffu, s, o);
        r[h] = s;
    }
    #pragma unroll
    for (int h = 0; h < H; h++)
        if (lane == h) out[(size_t)warp * H + h] = r[h];
}

// ---------------- layer 1 aggregation: warp per target, online softmax -------
__global__ __launch_bounds__(256) void gat_agg1(const int* __restrict__ src)
{
    int warp = (blockIdx.x * blockDim.x + threadIdx.x) >> 5;
    int lane = threadIdx.x & 31;
    if (warp >= NT1C) return;
    int myh = lane >> 3;                       // head for this lane's 8 features
    float ad = g_ad1[warp * 4 + myh];
    int beg = g_off1[warp], end = g_off1[warp + 1];
    float m = -1e30f, s = 0.f;
    float acc[8];
    #pragma unroll
    for (int j = 0; j < 8; j++) acc[j] = 0.f;

    for (int i = beg; i < end; i++) {
        int sn = src[g_eid1[i]];
        float ev = g_as1[(size_t)sn * 4 + myh] + ad;
        ev = ev > 0.f ? ev : NEG_SLOPE * ev;
        float nm = fmaxf(m, ev);
        float corr = __expf(m - nm);
        float w = __expf(ev - nm);
        s = s * corr + w;
        const float4* r = (const float4*)(g_xs1 + (size_t)sn * 256 + lane * 8);
        float4 r0 = r[0], r1 = r[1];
        acc[0] = acc[0] * corr + w * r0.x;
        acc[1] = acc[1] * corr + w * r0.y;
        acc[2] = acc[2] * corr + w * r0.z;
        acc[3] = acc[3] * corr + w * r0.w;
        acc[4] = acc[4] * corr + w * r1.x;
        acc[5] = acc[5] * corr + w * r1.y;
        acc[6] = acc[6] * corr + w * r1.z;
        acc[7] = acc[7] * corr + w * r1.w;
        m = nm;
    }
    float inv = 1.f / (s + 1e-16f);
    float* hp = g_h + (size_t)warp * 256 + lane * 8;
    float4 h0 = ((float4*)hp)[0], h1 = ((float4*)hp)[1];   // skip + bias
    float v[8];
    v[0] = acc[0] * inv + h0.x;  v[1] = acc[1] * inv + h0.y;
    v[2] = acc[2] * inv + h0.z;  v[3] = acc[3] * inv + h0.w;
    v[4] = acc[4] * inv + h1.x;  v[5] = acc[5] * inv + h1.y;
    v[6] = acc[6] * inv + h1.z;  v[7] = acc[7] * inv + h1.w;
    #pragma unroll
    for (int j = 0; j < 8; j++) v[j] = v[j] > 0.f ? v[j] : (__expf(v[j]) - 1.f);  // ELU
    float4 o0 = make_float4(v[0], v[1], v[2], v[3]);
    float4 o1 = make_float4(v[4], v[5], v[6], v[7]);
    ((float4*)hp)[0] = o0;
    ((float4*)hp)[1] = o1;
}

// ---------------- layer 2 aggregation (heads=1, hid=64) ----------------------
__global__ __launch_bounds__(256) void gat_agg2(const int* __restrict__ src)
{
    int warp = (blockIdx.x * blockDim.x + threadIdx.x) >> 5;
    int lane = threadIdx.x & 31;
    if (warp >= NT2C) return;
    float ad = g_ad2[warp];
    int beg = g_off2[warp], end = g_off2[warp + 1];
    float m = -1e30f, s = 0.f, a0 = 0.f, a1 = 0.f;
    for (int i = beg; i < end; i++) {
        int sn = src[g_eid2[i]];
        float ev = g_as2[sn] + ad;
        ev = ev > 0.f ? ev : NEG_SLOPE * ev;
        float nm = fmaxf(m, ev);
        float corr = __expf(m - nm);
        float w = __expf(ev - nm);
        s = s * corr + w;
        float2 r = *(const float2*)(g_xs2 + (size_t)sn * 64 + lane * 2);
        a0 = a0 * corr + w * r.x;
        a1 = a1 * corr + w * r.y;
        m = nm;
    }
    float inv = 1.f / (s + 1e-16f);
    float2* op = (float2*)(g_o + (size_t)warp * 64 + lane * 2);
    float2 o = *op;                  // skip2 + bias2
    o.x += a0 * inv;
    o.y += a1 * inv;
    *op = o;
}

// ---------------- log_softmax over 64 classes, warp per row -------------------
__global__ void logsoftmax_kernel(float* __restrict__ out)
{
    int warp = (blockIdx.x * blockDim.x + threadIdx.x) >> 5;
    int lane = threadIdx.x & 31;
    if (warp >= NT2C) return;
    float2 v = *(const float2*)(g_o + (size_t)warp * 64 + lane * 2);
    float mx = fmaxf(v.x, v.y);
    #pragma unroll
    for (int o = 16; o; o >>= 1) mx = fmaxf(mx, __shfl_xor_sync(0xffffffffu, mx, o));
    float se = __expf(v.x - mx) + __expf(v.y - mx);
    #pragma unroll
    for (int o = 16; o; o >>= 1) se += __shfl_xor_sync(0xffffffffu, se, o);
    float l = mx + logf(se);
    float2 r;
    r.x = v.x - l;
    r.y = v.y - l;
    *(float2*)(out + (size_t)warp * 64 + lane * 2) = r;
}

// ---------------- host launcher ----------------------------------------------
extern "C" void kernel_launch(void* const* d_in, const int* in_sizes, int n_in,
                              void* d_out, int out_size)
{
    const float* x    = (const float*)d_in[0];
    const int*   src1 = (const int*)d_in[1];
    const int*   dst1 = (const int*)d_in[2];
    const int*   src2 = (const int*)d_in[3];
    const int*   dst2 = (const int*)d_in[4];
    // d_in[5], d_in[6]: n_tgt1 / n_tgt2 scalars (compile-time constants here)
    const float* W1s  = (const float*)d_in[7];
    const float* W1d  = (const float*)d_in[8];
    const float* a1s  = (const float*)d_in[9];
    const float* a1d  = (const float*)d_in[10];
    const float* b1   = (const float*)d_in[11];
    const float* sk1W = (const float*)d_in[12];
    const float* sk1b = (const float*)d_in[13];
    const float* W2s  = (const float*)d_in[14];
    const float* W2d  = (const float*)d_in[15];
    const float* a2s  = (const float*)d_in[16];
    const float* a2d  = (const float*)d_in[17];
    const float* b2   = (const float*)d_in[18];
    const float* sk2W = (const float*)d_in[19];
    const float* sk2b = (const float*)d_in[20];

    int N0 = in_sizes[0] / KDIM;
    int E1 = in_sizes[1];
    int E2 = in_sizes[3];

    float *xs1, *hbuf, *xs2, *obuf, *as1, *ad1, *as2, *ad2;
    float *vS1, *vD1, *vS2, *vD2, *comb1, *comb2;
    int *cnt1, *off1, *cur1, *eid1, *cnt2, *off2, *cur2, *eid2;
    cudaGetSymbolAddress((void**)&xs1,  g_xs1);
    cudaGetSymbolAddress((void**)&hbuf, g_h);
    cudaGetSymbolAddress((void**)&xs2,  g_xs2);
    cudaGetSymbolAddress((void**)&obuf, g_o);
    cudaGetSymbolAddress((void**)&as1,  g_as1);
    cudaGetSymbolAddress((void**)&ad1,  g_ad1);
    cudaGetSymbolAddress((void**)&as2,  g_as2);
    cudaGetSymbolAddress((void**)&ad2,  g_ad2);
    cudaGetSymbolAddress((void**)&vS1,  g_vS1);
    cudaGetSymbolAddress((void**)&vD1,  g_vD1);
    cudaGetSymbolAddress((void**)&vS2,  g_vS2);
    cudaGetSymbolAddress((void**)&vD2,  g_vD2);
    cudaGetSymbolAddress((void**)&comb1, g_comb1);
    cudaGetSymbolAddress((void**)&comb2, g_comb2);
    cudaGetSymbolAddress((void**)&cnt1, g_cnt1);
    cudaGetSymbolAddress((void**)&off1, g_off1);
    cudaGetSymbolAddress((void**)&cur1, g_cur1);
    cudaGetSymbolAddress((void**)&eid1, g_eid1);
    cudaGetSymbolAddress((void**)&cnt2, g_cnt2);
    cudaGetSymbolAddress((void**)&off2, g_off2);
    cudaGetSymbolAddress((void**)&cur2, g_cur2);
    cudaGetSymbolAddress((void**)&eid2, g_eid2);

    // --- weight folding + combined biases ---
    fold_kernel<<<1, 256>>>(W1s, W1d, a1s, a1d, b1, sk1b,
                            W2s, W2d, a2s, a2d, b2, sk2b);

    // --- CSR build (both layers) ---
    zero_counts<<<CDIV(NT1C, 256), 256>>>();
    count_kernel<<<CDIV(E1, 256), 256>>>(dst1, cnt1, E1);
    count_kernel<<<CDIV(E2, 256), 256>>>(dst2, cnt2, E2);
    scan_kernel<<<1, 1024>>>(cnt1, off1, cur1, NT1C);
    scan_kernel<<<1, 1024>>>(cnt2, off2, cur2, NT2C);
    fill_kernel<<<CDIV(E1, 256), 256>>>(dst1, cur1, eid1, E1);
    fill_kernel<<<CDIV(E2, 256), 256>>>(dst2, cur2, eid2, E2);

    // --- layer 1 ---
    sgemm_k256<<<dim3(256 / GBN, CDIV(N0, GBM)), 256>>>(x, W1s, nullptr, xs1, N0, 256);
    rowdot_kernel<4><<<CDIV(N0 * 32, 256), 256>>>(x, vS1, as1, N0);
    rowdot_kernel<4><<<CDIV(NT1C * 32, 256), 256>>>(x, vD1, ad1, NT1C);
    sgemm_k256<<<dim3(256 / GBN, CDIV(NT1C, GBM)), 256>>>(x, sk1W, comb1, hbuf, NT1C, 256);
    gat_agg1<<<CDIV(NT1C * 32, 256), 256>>>(src1);

    // --- layer 2 ---
    sgemm_k256<<<dim3(64 / GBN, CDIV(NT1C, GBM)), 256>>>(hbuf, W2s, nullptr, xs2, NT1C, 64);
    rowdot_kernel<1><<<CDIV(NT1C * 32, 256), 256>>>(hbuf, vS2, as2, NT1C);
    rowdot_kernel<1><<<CDIV(NT2C * 32, 256), 256>>>(hbuf, vD2, ad2, NT2C);
    sgemm_k256<<<dim3(64 / GBN, CDIV(NT2C, GBM)), 256>>>(hbuf, sk2W, comb2, obuf, NT2C, 64);
    gat_agg2<<<CDIV(NT2C * 32, 256), 256>>>(src2);

    // --- output ---
    logsoftmax_kernel<<<CDIV(NT2C * 32, 256), 256>>>((float*)d_out);
}